// round 1
// baseline (speedup 1.0000x reference)
#include <cuda_runtime.h>
#include <cuda_bf16.h>

#define N_COLS 2048           // hidden dim
#define VECS_PER_ROW (N_COLS / 4)   // 512 float4
#define THREADS 256
#define VECS_PER_THREAD (VECS_PER_ROW / THREADS)  // 2
#define EPS 1e-5f

__global__ __launch_bounds__(THREADS)
void rmsnorm_kernel(const float4* __restrict__ x,
                    const float4* __restrict__ g,
                    float4* __restrict__ out)
{
    const int row = blockIdx.x;
    const float4* xr = x + (size_t)row * VECS_PER_ROW;
    float4* outr = out + (size_t)row * VECS_PER_ROW;

    const int t = threadIdx.x;

    // Front-batched loads: 2 independent LDG.128 per thread (MLP)
    float4 v0 = xr[t];
    float4 v1 = xr[t + THREADS];

    float ss = v0.x * v0.x + v0.y * v0.y + v0.z * v0.z + v0.w * v0.w
             + v1.x * v1.x + v1.y * v1.y + v1.z * v1.z + v1.w * v1.w;

    // Warp reduce
    #pragma unroll
    for (int off = 16; off > 0; off >>= 1)
        ss += __shfl_xor_sync(0xFFFFFFFFu, ss, off);

    // Block reduce across 8 warps
    __shared__ float warp_sums[THREADS / 32];
    __shared__ float s_scale;
    const int warp = t >> 5;
    const int lane = t & 31;
    if (lane == 0) warp_sums[warp] = ss;
    __syncthreads();
    if (warp == 0) {
        float s = (lane < THREADS / 32) ? warp_sums[lane] : 0.0f;
        #pragma unroll
        for (int off = 4; off > 0; off >>= 1)
            s += __shfl_xor_sync(0xFFFFFFFFu, s, off);
        if (lane == 0)
            s_scale = rsqrtf(s * (1.0f / (float)N_COLS) + EPS);
    }
    __syncthreads();
    const float scale = s_scale;

    // g loads hit L2/L1 (8 KB, broadcast across all rows)
    float4 g0 = g[t];
    float4 g1 = g[t + THREADS];

    float4 o0, o1;
    o0.x = v0.x * scale * g0.x;
    o0.y = v0.y * scale * g0.y;
    o0.z = v0.z * scale * g0.z;
    o0.w = v0.w * scale * g0.w;
    o1.x = v1.x * scale * g1.x;
    o1.y = v1.y * scale * g1.y;
    o1.z = v1.z * scale * g1.z;
    o1.w = v1.w * scale * g1.w;

    outr[t] = o0;
    outr[t + THREADS] = o1;
}

extern "C" void kernel_launch(void* const* d_in, const int* in_sizes, int n_in,
                              void* d_out, int out_size)
{
    const float4* x = (const float4*)d_in[0];
    const float4* g = (const float4*)d_in[1];
    float4* out = (float4*)d_out;

    const int n_rows = in_sizes[0] / N_COLS;  // 16384

    rmsnorm_kernel<<<n_rows, THREADS>>>(x, g, out);
}